// round 16
// baseline (speedup 1.0000x reference)
#include <cuda_runtime.h>
#include <math.h>
#include <float.h>
#include <stdint.h>

// WaveNet autoregressive generation, sm_103a — round 15: 2-CTA cluster
// channel-split. 64 clusters x 2 CTAs (=128 CTAs, single wave), each cluster
// owns 2 rows; BOTH CTAs carry both rows' activations, but each CTA loads only
// HALF of every weight matrix (conv: its 64 of 128 output cols; res/skip/head:
// its half of the k-rows). This halves the per-SM L1tex weight-byte floor
// (the measured binding resource in R12: L1=50%, 38K wf/step of 72K cyc).
// k-splits make skip + head need no per-layer exchange; only the res partial
// (128 floats) crosses CTAs each layer via DSMEM + mbarrier full/empty credits.
// Rank-ordered symmetric sums keep both CTAs bit-identical (shared argmax).

#define NLAYER 30
#define BB 128
#define VV 256
#define RING_PER_ROW 3069   // 3 * (2^10 - 1) slots, 64 floats each

__device__ float g_ring[(size_t)BB * RING_PER_ROW * 64];  // ~100.6 MB scratch

#define BAR_MAIN() asm volatile("bar.sync 1, 256;" ::: "memory")

// ---- cluster / mbarrier helpers ----
__device__ __forceinline__ uint32_t smem_u32(const void* p) {
    uint32_t a;
    asm("{ .reg .u64 t; cvta.to.shared.u64 t, %1; cvt.u32.u64 %0, t; }"
        : "=r"(a) : "l"(p));
    return a;
}
__device__ __forceinline__ uint32_t cluster_rank() {
    uint32_t r; asm("mov.u32 %0, %%cluster_ctarank;" : "=r"(r)); return r;
}
__device__ __forceinline__ uint32_t mapa_peer(uint32_t laddr, uint32_t peer) {
    uint32_t r;
    asm("mapa.shared::cluster.u32 %0, %1, %2;" : "=r"(r) : "r"(laddr), "r"(peer));
    return r;
}
__device__ __forceinline__ void st_remote_f32(uint32_t raddr, float v) {
    asm volatile("st.shared::cluster.f32 [%0], %1;" :: "r"(raddr), "f"(v) : "memory");
}
__device__ __forceinline__ void mbar_init(uint32_t a, uint32_t cnt) {
    asm volatile("mbarrier.init.shared.b64 [%0], %1;" :: "r"(a), "r"(cnt) : "memory");
}
__device__ __forceinline__ void mbar_arrive_remote(uint32_t raddr) {
    asm volatile("mbarrier.arrive.release.cluster.shared::cluster.b64 _, [%0];"
                 :: "r"(raddr) : "memory");
}
__device__ __forceinline__ void mbar_wait(uint32_t a, int parity) {
    asm volatile(
        "{\n\t.reg .pred P;\n\t"
        "LW_%=:\n\t"
        "mbarrier.try_wait.parity.acquire.cluster.shared::cta.b64 P, [%0], %1, 0x989680;\n\t"
        "@P bra.uni LD_%=;\n\t"
        "bra.uni LW_%=;\n\t"
        "LD_%=:\n\t}"
        :: "r"(a), "r"((uint32_t)parity) : "memory");
}
#define CLUSTER_SYNC() do { \
    asm volatile("barrier.cluster.arrive.aligned;" ::: "memory"); \
    asm volatile("barrier.cluster.wait.aligned;" ::: "memory"); } while (0)

// ---- matvec helpers (2 rows per thread, weights shared) ----
template<int N>
__device__ __forceinline__ void wload(float4* dst, const float4* __restrict__ Wg,
                                      int s4) {
#pragma unroll
    for (int u = 0; u < N; u++) dst[u] = Wg[(size_t)u * s4];
}
template<int N>
__device__ __forceinline__ void mm_reg(const float* __restrict__ a0,
                                       const float* __restrict__ a1,
                                       const float4* w, float4& o0, float4& o1) {
#pragma unroll
    for (int c2 = 0; c2 < N; c2++) {
        float x0 = a0[c2], x1 = a1[c2];
        const float4 wv = w[c2];
        o0.x = fmaf(x0, wv.x, o0.x); o0.y = fmaf(x0, wv.y, o0.y);
        o0.z = fmaf(x0, wv.z, o0.z); o0.w = fmaf(x0, wv.w, o0.w);
        o1.x = fmaf(x1, wv.x, o1.x); o1.y = fmaf(x1, wv.y, o1.y);
        o1.z = fmaf(x1, wv.z, o1.z); o1.w = fmaf(x1, wv.w, o1.w);
    }
}
template<int N>
__device__ __forceinline__ void mm_gl(const float* __restrict__ a0,
                                      const float* __restrict__ a1,
                                      const float4* __restrict__ Wg, int s4,
                                      float4& o0, float4& o1) {
#pragma unroll
    for (int c2 = 0; c2 < N; c2++) {
        const float4 wv = Wg[(size_t)c2 * s4];
        float x0 = a0[c2], x1 = a1[c2];
        o0.x = fmaf(x0, wv.x, o0.x); o0.y = fmaf(x0, wv.y, o0.y);
        o0.z = fmaf(x0, wv.z, o0.z); o0.w = fmaf(x0, wv.w, o0.w);
        o1.x = fmaf(x1, wv.x, o1.x); o1.y = fmaf(x1, wv.y, o1.y);
        o1.z = fmaf(x1, wv.z, o1.z); o1.w = fmaf(x1, wv.w, o1.w);
    }
}

__global__ __launch_bounds__(384, 1)
void wavenet_kernel(const int* __restrict__ seed,
                    const float* __restrict__ emb,     // (V, 64)
                    const float* __restrict__ kern,    // (L, 2, 64, 128)
                    const float* __restrict__ cbias,   // (L, 128)
                    const float* __restrict__ rw,      // (L, 64, 64)
                    const float* __restrict__ rb,      // (L, 64)
                    const float* __restrict__ sw,      // (L, 64, 256)
                    const float* __restrict__ sb,      // (L, 256)
                    const float* __restrict__ ow0,     // (256, 256)
                    const float* __restrict__ ob0,     // (256)
                    const float* __restrict__ ow1,     // (256, 256)
                    const float* __restrict__ ob1,     // (256)
                    float* __restrict__ out,
                    int T, long long samp_off, long long logit_off, int mode)
{
    __shared__ __align__(16) float sx[2][64];           // full x, both rows
    __shared__ __align__(16) float sxl[2][64];          // full x_last
    __shared__ __align__(16) float sgb[2][2][32];       // own gate half, dbl-buf
    __shared__ __align__(16) float sxch[2][2][64];      // res-partial inbox
    __shared__ __align__(16) float hxch[2][256];        // head-partial inbox
    __shared__ __align__(16) float ssk[2][256];
    __shared__ __align__(16) float sh0[2][256];
    __shared__ __align__(16) float slg[2][256];
    __shared__ __align__(16) float cbs[NLAYER * 64];    // own-half conv bias
    __shared__ __align__(16) float ssb[256];            // sum of skip biases
    __shared__ __align__(16) float obs0[256], obs1[256];
    __shared__ __align__(16) float pbuf[2048];          // 8KB partials union
    __shared__ __align__(8) unsigned long long mb[6];   // lf0 lf1 le0 le1 hf he
    __shared__ int snidx[2];

    float (*scp)[2][64]  = (float(*)[2][64])pbuf;    // [16][2][64] conv
    float (*srp)[2][64]  = (float(*)[2][64])pbuf;    // [16][2][64] res
    float (*ssp)[2][256] = (float(*)[2][256])pbuf;   // [4][2][256] skip/head

    const int tid = threadIdx.x;
    const int rank = (int)cluster_rank();              // 0 or 1
    const int peer = rank ^ 1;
    const int row0 = (int)(blockIdx.x & ~1u);          // cluster's first row
    const bool is_main = tid < 256;

    // ---- thread mappings ----
    // conv: 16 local j-quads x 16 k-splits (ks<8: K0 rows, ks>=8: K1 rows)
    const int jqc = tid & 15, ksc = tid >> 4;
    const int cmat = ksc >> 3, kbc = (ksc & 7) * 8;
    const int gqc = (jqc < 8) ? (8 * rank + jqc) : (16 + 8 * rank + (jqc - 8));
    // res: 16 j-quads (all 64 cols) x 16 k-splits of 2 over own k-half
    const int jqr = tid & 15, ksr = tid >> 4;
    // head m0/m1: 64 j-quads x 4 k-splits of 32 over own k-half (tid<256)
    const int jqh = tid & 63, ksh = (tid >> 6) & 3, kbh = ksh * 32;
    // skip group (tid>=256): 64 j-quads x 2 k-splits of 16 over own k-half
    const int st = tid & 127;
    const int jqs = st & 63, kss = st >> 6, kbs = kss * 16;
    // scalar mappings
    const int r2 = (tid >> 6) & 1, ch = tid & 63;      // tid<128: (row, ch)
    const int chh = tid;                               // tid<256 head combine

    float4 wk[8];   // conv rows (4) or head rows (8)
    float4 wr[2];   // res prefetch
    float4 osk0 = {0,0,0,0}, osk1 = {0,0,0,0};
    float  rpop = 0.f, rbv = 0.f;
    int lf[2] = {0, 0}, le[2] = {1, 1}, hf = 0, he = 1;   // mbar parities

    // ---- mbarrier addresses ----
    const uint32_t a_mb = smem_u32(mb);
    const uint32_t a_lfull[2]  = {a_mb,      a_mb + 8};
    const uint32_t a_lempty[2] = {a_mb + 16, a_mb + 24};
    const uint32_t a_hfull = a_mb + 32, a_hempty = a_mb + 40;
    const uint32_t p_lfull[2]  = {mapa_peer(a_lfull[0], peer),
                                  mapa_peer(a_lfull[1], peer)};
    const uint32_t p_lempty[2] = {mapa_peer(a_lempty[0], peer),
                                  mapa_peer(a_lempty[1], peer)};
    const uint32_t p_hfull  = mapa_peer(a_hfull, peer);
    const uint32_t p_hempty = mapa_peer(a_hempty, peer);
    const uint32_t p_sxch = mapa_peer(smem_u32(sxch), peer);
    const uint32_t p_hxch = mapa_peer(smem_u32(hxch), peer);

    // ---- one-time staging ----
    if (tid == 0) {
        mbar_init(a_lfull[0], 128);  mbar_init(a_lfull[1], 128);
        mbar_init(a_lempty[0], 128); mbar_init(a_lempty[1], 128);
        mbar_init(a_hfull, 256);     mbar_init(a_hempty, 256);
    }
    for (int idx = tid; idx < NLAYER * 64; idx += 384) {
        int i = idx >> 6, q = idx & 63;
        cbs[idx] = (q < 32) ? cbias[i * 128 + 32 * rank + q]
                            : cbias[i * 128 + 64 + 32 * rank + (q - 32)];
    }
    if (tid < 256) {
        float s = 0.f;
#pragma unroll 1
        for (int i = 0; i < NLAYER; i++) s += sb[i * 256 + tid];
        ssb[tid] = s;
        obs0[tid] = ob0[tid];
        obs1[tid] = ob1[tid];
    }
    if (tid < 2) snidx[tid] = seed[row0 + tid];
    if (is_main)   // prefetch conv (t=0, layer 0)
        wload<4>(wk, (const float4*)kern + ((size_t)cmat * 64 + kbc) * 32 + gqc, 32);
    __syncthreads();
    CLUSTER_SYNC();   // mbarriers visible cluster-wide before any remote op

#pragma unroll 1
    for (int t = 0; t < T; t++) {
        // ---- step head ----
        if (tid < 128) {
            sx[r2][ch] = emb[(size_t)snidx[r2] * 64 + ch];
            sxl[r2][ch] = rpop;
        }
        if (!is_main) { osk0 = make_float4(0,0,0,0); osk1 = make_float4(0,0,0,0); }

#pragma unroll 1
        for (int i = 0; i < NLAYER; i++) {
            __syncthreads();   // sx_i full; sgb[i-1] own half ready
            const int b = i & 1;

            if (is_main) {
                const int d = 1 << (i % 10);
                const long long off = (long long)(i / 10) * 1023 + (d - 1);

                // -- A: conv partials (own 64 of 128 cols; 4 pre + 4 stream)
                {
                    const float4* K = (const float4*)kern
                        + ((size_t)(i * 2 + cmat) * 64 + kbc) * 32 + gqc;
                    const float* a0 = (cmat ? sx[0] : sxl[0]) + kbc;
                    const float* a1 = (cmat ? sx[1] : sxl[1]) + kbc;
                    float4 o0 = {0,0,0,0}, o1 = {0,0,0,0};
                    mm_reg<4>(a0,     a1,     wk, o0, o1);
                    mm_gl<4> (a0 + 4, a1 + 4, K + 4 * 32, 32, o0, o1);
                    *(float4*)&scp[ksc][0][4 * jqc] = o0;
                    *(float4*)&scp[ksc][1][4 * jqc] = o1;
                }
                if (tid < 128) {
                    if (rank == 0) {   // one pusher; ordered by mbar chains
                        size_t idx = ((size_t)(row0 + r2) * RING_PER_ROW
                                      + (size_t)off + (t & (d - 1))) * 64 + ch;
                        g_ring[idx] = sx[r2][ch];
                    }
                    rbv = rb[i * 64 + ch];
                }
                wload<2>(wr, (const float4*)rw
                             + ((size_t)i * 64 + 32 * rank + 2 * ksr) * 16 + jqr, 16);
                BAR_MAIN();

                // -- B: gate (own 32 ch x 2 rows) + next conv prefetch + pop
                if (i < NLAYER - 1) {
                    const float4* KN = (const float4*)kern
                        + ((size_t)((i + 1) * 2 + cmat) * 64 + kbc) * 32 + gqc;
                    wload<4>(wk, KN, 32);
                    if (tid < 128) {
                        const int d2 = 1 << ((i + 1) % 10);
                        const long long off2 = (long long)((i + 1) / 10) * 1023 + (d2 - 1);
                        size_t idx2 = ((size_t)(row0 + r2) * RING_PER_ROW
                                       + (size_t)off2 + (t & (d2 - 1))) * 64 + ch;
                        rpop = (t >= d2) ? g_ring[idx2] : 0.f;
                    }
                } else {
                    wload<8>(wk, (const float4*)ow0
                                 + ((size_t)128 * rank + kbh) * 64 + jqh, 64);
                }
                if (tid < 64) {
                    int rr = tid >> 5, lc = tid & 31;
                    float ht = cbs[i * 64 + lc], hs = cbs[i * 64 + 32 + lc];
                    float pt = 0.f, ps = 0.f;
#pragma unroll
                    for (int s2 = 0; s2 < 16; s2 += 4) {
                        pt += (scp[s2][rr][lc]      + scp[s2+1][rr][lc])
                            + (scp[s2+2][rr][lc]    + scp[s2+3][rr][lc]);
                        ps += (scp[s2][rr][32+lc]   + scp[s2+1][rr][32+lc])
                            + (scp[s2+2][rr][32+lc] + scp[s2+3][rr][32+lc]);
                    }
                    ht += pt; hs += ps;
                    float e2 = __expf(2.f * ht);
                    float th = 1.f - __fdividef(2.f, e2 + 1.f);
                    float sig = __fdividef(1.f, 1.f + __expf(-hs));
                    sgb[b][rr][lc] = th * sig;
                }
                BAR_MAIN();

                // -- C: res partials (all 64 cols, own k-half, prefetched)
                {
                    float4 o0 = {0,0,0,0}, o1 = {0,0,0,0};
                    mm_reg<2>(sgb[b][0] + 2 * ksr, sgb[b][1] + 2 * ksr, wr, o0, o1);
                    *(float4*)&srp[ksr][0][4 * jqr] = o0;
                    *(float4*)&srp[ksr][1][4 * jqr] = o1;
                }
                BAR_MAIN();

                // -- D: res combine + cross-CTA partial exchange (full/empty)
                if (tid < 128) {
                    float part = 0.f;
#pragma unroll
                    for (int s2 = 0; s2 < 16; s2 += 4)
                        part += (srp[s2][r2][ch]   + srp[s2+1][r2][ch])
                              + (srp[s2+2][r2][ch] + srp[s2+3][r2][ch]);
                    mbar_wait(a_lempty[b], le[b]); le[b] ^= 1;
                    st_remote_f32(p_sxch + (size_t)(b * 128 + r2 * 64 + ch) * 4, part);
                    mbar_arrive_remote(p_lfull[b]);
                    mbar_wait(a_lfull[b], lf[b]); lf[b] ^= 1;
                    float pp = sxch[b][r2][ch];
                    mbar_arrive_remote(p_lempty[b]);
                    float pa = rank ? pp : part, pb = rank ? part : pp;
                    sx[r2][ch] += rbv + (pa + pb);   // identical in both CTAs
                    if (i < NLAYER - 1) sxl[r2][ch] = rpop;
                }
            } else {
                // ---- skip group: lagged skip of layer i-1, own k-half ----
                if (i > 0) {
                    const float4* SW = (const float4*)sw
                        + ((size_t)(i - 1) * 64 + 32 * rank + kbs) * 64 + jqs;
                    mm_gl<16>(sgb[(i - 1) & 1][0] + kbs, sgb[(i - 1) & 1][1] + kbs,
                              SW, 64, osk0, osk1);
                }
            }
        }
        __syncthreads();   // P_30

        // ---- tail: skip_29 (skip group); main already has ow0 rows in wk ----
        if (!is_main) {
            const float4* SW = (const float4*)sw
                + ((size_t)(NLAYER - 1) * 64 + 32 * rank + kbs) * 64 + jqs;
            mm_gl<16>(sgb[(NLAYER - 1) & 1][0] + kbs, sgb[(NLAYER - 1) & 1][1] + kbs,
                      SW, 64, osk0, osk1);
            *(float4*)&ssp[kss][0][4 * jqs] = osk0;
            *(float4*)&ssp[kss][1][4 * jqs] = osk1;
        }
        __syncthreads();

        // ---- skip partial exchange -> full ssk (both CTAs, symmetric) ----
        if (is_main) {
            float p0 = ssp[0][0][chh] + ssp[1][0][chh];
            float p1 = ssp[0][1][chh] + ssp[1][1][chh];
            mbar_wait(a_hempty, he); he ^= 1;
            st_remote_f32(p_hxch + (size_t)chh * 4, p0);
            st_remote_f32(p_hxch + (size_t)(256 + chh) * 4, p1);
            mbar_arrive_remote(p_hfull);
            mbar_wait(a_hfull, hf); hf ^= 1;
            float q0 = hxch[0][chh], q1 = hxch[1][chh];
            mbar_arrive_remote(p_hempty);
            float a0 = rank ? q0 : p0, b0 = rank ? p0 : q0;
            float a1 = rank ? q1 : p1, b1 = rank ? p1 : q1;
            ssk[0][chh] = fmaxf((a0 + b0) + ssb[chh], 0.f);
            ssk[1][chh] = fmaxf((a1 + b1) + ssb[chh], 0.f);
        }
        __syncthreads();

        // ---- head m0: partial h0 over own k-half (8 pre + 24 stream) ----
        if (is_main) {
            const float4* W = (const float4*)ow0
                + ((size_t)128 * rank + kbh) * 64 + jqh;
            const float* a0 = ssk[0] + 128 * rank + kbh;
            const float* a1 = ssk[1] + 128 * rank + kbh;
            float4 o0 = {0,0,0,0}, o1 = {0,0,0,0};
            mm_reg<8>(a0, a1, wk, o0, o1);
            mm_gl<24>(a0 + 8, a1 + 8, W + 8 * 64, 64, o0, o1);
            wload<8>(wk, (const float4*)ow1
                         + ((size_t)128 * rank + kbh) * 64 + jqh, 64);
            *(float4*)&ssp[ksh][0][4 * jqh] = o0;
            *(float4*)&ssp[ksh][1][4 * jqh] = o1;
        }
        __syncthreads();
        if (is_main) {
            float p0 = (ssp[0][0][chh] + ssp[1][0][chh])
                     + (ssp[2][0][chh] + ssp[3][0][chh]);
            float p1 = (ssp[0][1][chh] + ssp[1][1][chh])
                     + (ssp[2][1][chh] + ssp[3][1][chh]);
            mbar_wait(a_hempty, he); he ^= 1;
            st_remote_f32(p_hxch + (size_t)chh * 4, p0);
            st_remote_f32(p_hxch + (size_t)(256 + chh) * 4, p1);
            mbar_arrive_remote(p_hfull);
            mbar_wait(a_hfull, hf); hf ^= 1;
            float q0 = hxch[0][chh], q1 = hxch[1][chh];
            mbar_arrive_remote(p_hempty);
            float a0 = rank ? q0 : p0, b0 = rank ? p0 : q0;
            float a1 = rank ? q1 : p1, b1 = rank ? p1 : q1;
            sh0[0][chh] = fmaxf((a0 + b0) + obs0[chh], 0.f);
            sh0[1][chh] = fmaxf((a1 + b1) + obs0[chh], 0.f);
        }
        __syncthreads();

        // ---- head m1: partial logits; prefetch next conv + layer-0 pop ----
        if (is_main) {
            const float4* W = (const float4*)ow1
                + ((size_t)128 * rank + kbh) * 64 + jqh;
            const float* a0 = sh0[0] + 128 * rank + kbh;
            const float* a1 = sh0[1] + 128 * rank + kbh;
            float4 o0 = {0,0,0,0}, o1 = {0,0,0,0};
            mm_reg<8>(a0, a1, wk, o0, o1);
            mm_gl<24>(a0 + 8, a1 + 8, W + 8 * 64, 64, o0, o1);
            wload<4>(wk, (const float4*)kern
                         + ((size_t)cmat * 64 + kbc) * 32 + gqc, 32);
            if (tid < 128)
                rpop = g_ring[((size_t)(row0 + r2) * RING_PER_ROW) * 64 + ch];
            *(float4*)&ssp[ksh][0][4 * jqh] = o0;
            *(float4*)&ssp[ksh][1][4 * jqh] = o1;
        }
        __syncthreads();
        if (is_main) {
            float p0 = (ssp[0][0][chh] + ssp[1][0][chh])
                     + (ssp[2][0][chh] + ssp[3][0][chh]);
            float p1 = (ssp[0][1][chh] + ssp[1][1][chh])
                     + (ssp[2][1][chh] + ssp[3][1][chh]);
            mbar_wait(a_hempty, he); he ^= 1;
            st_remote_f32(p_hxch + (size_t)chh * 4, p0);
            st_remote_f32(p_hxch + (size_t)(256 + chh) * 4, p1);
            mbar_arrive_remote(p_hfull);
            mbar_wait(a_hfull, hf); hf ^= 1;
            float q0 = hxch[0][chh], q1 = hxch[1][chh];
            mbar_arrive_remote(p_hempty);
            float a0 = rank ? q0 : p0, b0 = rank ? p0 : q0;
            float a1 = rank ? q1 : p1, b1 = rank ? p1 : q1;
            float v0 = (a0 + b0) + obs1[chh];
            float v1 = (a1 + b1) + obs1[chh];
            slg[0][chh] = v0;
            slg[1][chh] = v1;
            if (rank == 0 && (mode & 2)) {
                out[logit_off + ((size_t)(row0 + 0) * T + t) * VV + chh] = v0;
                out[logit_off + ((size_t)(row0 + 1) * T + t) * VV + chh] = v1;
            }
        }
        __syncthreads();

        // ---- argmax per row (both CTAs identical; rank0 writes samples) ----
        if (tid < 64) {
            int rr = tid >> 5, lane = tid & 31;
            float bv = -FLT_MAX;
            int bi = 0;
#pragma unroll
            for (int jj = 0; jj < 8; jj++) {
                int j = lane + jj * 32;
                float v = slg[rr][j];
                if (v > bv) { bv = v; bi = j; }
            }
#pragma unroll
            for (int o2 = 16; o2 > 0; o2 >>= 1) {
                float ov = __shfl_down_sync(0xffffffffu, bv, o2);
                int   oi = __shfl_down_sync(0xffffffffu, bi, o2);
                if (ov > bv || (ov == bv && oi < bi)) { bv = ov; bi = oi; }
            }
            if (lane == 0) {
                snidx[rr] = bi;
                if (rank == 0) {
                    if (mode & 1) out[samp_off + (size_t)(row0 + rr) * T + t] = (float)bi;
                    if (mode & 4) ((int*)out)[(size_t)(row0 + rr) * T + t] = bi;
                }
            }
        }
        __syncthreads();
    }
    CLUSTER_SYNC();   // no CTA exits while peer may still arrive on its mbars
}

extern "C" void kernel_launch(void* const* d_in, const int* in_sizes, int n_in,
                              void* d_out, int out_size) {
    const int*   seed  = (const int*)d_in[0];
    const float* emb   = (const float*)d_in[1];
    const float* kern  = (const float*)d_in[2];
    const float* cbias = (const float*)d_in[3];
    const float* rw    = (const float*)d_in[4];
    const float* rb    = (const float*)d_in[5];
    const float* sw    = (const float*)d_in[6];
    const float* sb    = (const float*)d_in[7];
    const float* ow0   = (const float*)d_in[8];
    const float* ob0   = (const float*)d_in[9];
    const float* ow1   = (const float*)d_in[10];
    const float* ob1   = (const float*)d_in[11];
    (void)in_sizes; (void)n_in;

    int T, mode;
    long long samp_off = 0, logit_off = 0;
    if (out_size % (BB * (VV + 1)) == 0) {
        T = out_size / (BB * (VV + 1));
        mode = 1 | 2;                       // float samples then logits
        samp_off = 0;
        logit_off = (long long)BB * T;
    } else if (out_size % (BB * VV) == 0) {
        T = out_size / (BB * VV);
        mode = 2;                           // logits only
        logit_off = 0;
    } else {
        T = out_size / BB;
        mode = 4;                           // int32 samples only
    }

    float* o = (float*)d_out;
    cudaLaunchConfig_t cfg = {};
    cfg.gridDim = dim3(BB, 1, 1);           // 128 CTAs = 64 clusters of 2
    cfg.blockDim = dim3(384, 1, 1);
    cudaLaunchAttribute attrs[1];
    attrs[0].id = cudaLaunchAttributeClusterDimension;
    attrs[0].val.clusterDim.x = 2;
    attrs[0].val.clusterDim.y = 1;
    attrs[0].val.clusterDim.z = 1;
    cfg.attrs = attrs;
    cfg.numAttrs = 1;
    cudaLaunchKernelEx(&cfg, wavenet_kernel, seed, emb, kern, cbias, rw, rb,
                       sw, sb, ow0, ob0, ow1, ob1, o, T, samp_off, logit_off, mode);
}

// round 17
// speedup vs baseline: 1.5787x; 1.5787x over previous
#include <cuda_runtime.h>
#include <math.h>
#include <float.h>

// WaveNet autoregressive generation, sm_103a — round 16: K0-lookahead.
// Base = round-12 winner (128 CTAs x 1 row; 384 thr: 256 main + 128 background).
// The conv is x_last@K0 + x@K1. x_last (dilation-queue pop) is available one
// full layer early, so the background group computes layer i+1's K0 partials
// during layer i (reading acts straight from g_ring), alongside the lagged
// skip matmul. Main's critical path shrinks to K1-conv + gate + res: the K0
// weight stream (256 wf/layer) and the pop's L2 round-trip leave it entirely.
// Layer 0 of step t+1 is precomputed at iteration 29. K0 partials live in a
// layer-parity double buffer; the (t >= d) guard keeps graph replays exact.

#define NLAYER 30
#define BB 128
#define VV 256
#define RING_PER_ROW 3069   // 3 * (2^10 - 1) slots, 64 floats each

__device__ float g_ring[(size_t)BB * RING_PER_ROW * 64];  // ~100.6 MB scratch

#define BAR_MAIN() asm volatile("bar.sync 1, 256;" ::: "memory")

template<int N>
__device__ __forceinline__ void wload(float4* dst, const float4* __restrict__ Wg,
                                      int s4) {
#pragma unroll
    for (int u = 0; u < N; u++) dst[u] = Wg[(size_t)u * s4];
}

// FMA N k-steps (N%4==0), one row, weights from a register buffer.
template<int N>
__device__ __forceinline__ void mm_reg(const float* __restrict__ a0,
                                       const float4* w, float4& o0) {
#pragma unroll
    for (int c2 = 0; c2 < N; c2 += 4) {
        float v0[4];
        *(float4*)v0 = *(const float4*)(a0 + c2);
#pragma unroll
        for (int u = 0; u < 4; u++) {
            const float4 wv = w[c2 + u];
            o0.x = fmaf(v0[u], wv.x, o0.x);
            o0.y = fmaf(v0[u], wv.y, o0.y);
            o0.z = fmaf(v0[u], wv.z, o0.z);
            o0.w = fmaf(v0[u], wv.w, o0.w);
        }
    }
}

// FMA N k-steps streaming weights from global (independent LDGs pipeline).
template<int N>
__device__ __forceinline__ void mm_gl(const float* __restrict__ a0,
                                      const float4* __restrict__ Wg, int s4,
                                      float4& o0) {
#pragma unroll
    for (int c2 = 0; c2 < N; c2 += 4) {
        float v0[4];
        *(float4*)v0 = *(const float4*)(a0 + c2);
#pragma unroll
        for (int u = 0; u < 4; u++) {
            const float4 wv = Wg[(size_t)(c2 + u) * s4];
            o0.x = fmaf(v0[u], wv.x, o0.x);
            o0.y = fmaf(v0[u], wv.y, o0.y);
            o0.z = fmaf(v0[u], wv.z, o0.z);
            o0.w = fmaf(v0[u], wv.w, o0.w);
        }
    }
}

// FMA N k-steps, activations in registers (for background K0 from g_ring).
template<int N>
__device__ __forceinline__ void mm_ra(const float* a0,
                                      const float4* __restrict__ Wg, int s4,
                                      float4& o0) {
#pragma unroll
    for (int u = 0; u < N; u++) {
        const float4 wv = Wg[(size_t)u * s4];
        o0.x = fmaf(a0[u], wv.x, o0.x);
        o0.y = fmaf(a0[u], wv.y, o0.y);
        o0.z = fmaf(a0[u], wv.z, o0.z);
        o0.w = fmaf(a0[u], wv.w, o0.w);
    }
}

__global__ __launch_bounds__(384, 1)
void wavenet_kernel(const int* __restrict__ seed,
                    const float* __restrict__ emb,     // (V, 64)
                    const float* __restrict__ kern,    // (L, 2, 64, 128)
                    const float* __restrict__ cbias,   // (L, 128)
                    const float* __restrict__ rw,      // (L, 64, 64)
                    const float* __restrict__ rb,      // (L, 64)
                    const float* __restrict__ sw,      // (L, 64, 256)
                    const float* __restrict__ sb,      // (L, 256)
                    const float* __restrict__ ow0,     // (256, 256)
                    const float* __restrict__ ob0,     // (256)
                    const float* __restrict__ ow1,     // (256, 256)
                    const float* __restrict__ ob1,     // (256)
                    float* __restrict__ out,
                    int T, long long samp_off, long long logit_off, int mode)
{
    __shared__ __align__(16) float sx[64];
    __shared__ __align__(16) float sgb[2][64];          // double-buffered gate
    __shared__ __align__(16) float cp0[2][4][128];      // K0 partials, dbl-buf
    __shared__ __align__(16) float ssk[256];
    __shared__ __align__(16) float sh0[256];
    __shared__ __align__(16) float slg[256];
    __shared__ __align__(16) float cbs[NLAYER * 128];   // staged conv bias
    __shared__ __align__(16) float ssb[256];            // sum of skip biases
    __shared__ __align__(16) float obs0[256], obs1[256];
    __shared__ __align__(16) float pbuf[1536];          // 6KB partials union
    __shared__ int snidx;

    float (*scp)[128] = (float(*)[128])pbuf;   // [8][128] conv K1
    float (*srp)[64]  = (float(*)[64])pbuf;    // [16][64] res
    float (*ssp)[256] = (float(*)[256])pbuf;   // [6][256] skip/head

    const int tid = threadIdx.x;
    const int row = blockIdx.x;
    const bool is_main = tid < 256;

    // main mappings
    const int jqc = tid & 31, ksc = tid >> 5, kbc = ksc * 8;   // K1: 32jq x 8ks
    const int jqr = tid & 15, ksr = tid >> 4, kbr = ksr * 4;   // res 16jq x 16ks
    const int c = tid;                                         // tid<64 scalar
    const int ch = tid;                                        // tid<256 combines
    // head mapping over ALL 384 threads: 64jq x 6ks, k = {48,48,48,48,32,32}
    const int jqh = tid & 63, ksh = tid >> 6;
    const int khb = (ksh < 4) ? ksh * 48 : 192 + (ksh - 4) * 32;
    // background mappings (tid >= 256, 128 threads)
    const int st = tid & 127;
    const int jqs = st & 63, kss = st >> 6, kbs = kss * 32;    // skip 64jq x 2ks
    const int jq0 = st & 31, ks0 = st >> 5, kb0 = ks0 * 16;    // K0   32jq x 4ks

    float4 wk[8];   // main: conv K1 rows kbc..kbc+3 (4 used); head rows (8)
    float4 wr[4];   // main: res prefetch
    float4 osk = {0, 0, 0, 0};  // background skip accumulator

    // ---- one-time staging ----
    for (int idx = tid; idx < NLAYER * 128; idx += 384) cbs[idx] = cbias[idx];
    for (int idx = tid; idx < 1024; idx += 384)
        ((float*)cp0)[idx] = 0.f;                // K0 partials start at zero
    if (tid < 256) {
        float s = 0.f;
#pragma unroll 1
        for (int i = 0; i < NLAYER; i++) s += sb[i * 256 + tid];
        ssb[tid] = s;
        obs0[tid] = ob0[tid];
        obs1[tid] = ob1[tid];
    }
    if (tid == 0) snidx = seed[row];
    if (is_main)   // prefetch conv K1 (t=0, layer 0)
        wload<4>(wk, (const float4*)kern + (size_t)(64 + kbc) * 32 + jqc, 32);
    __syncthreads();

#pragma unroll 1
    for (int t = 0; t < T; t++) {
        // ---- step head ----
        if (tid < 64) sx[c] = emb[(size_t)snidx * 64 + c];
        if (!is_main) { osk.x = osk.y = osk.z = osk.w = 0.f; }

#pragma unroll 1
        for (int i = 0; i < NLAYER; i++) {
            __syncthreads();   // sx_i ready; cp0[i&1] ready; sg[i-1] ready

            if (is_main) {
                const int d = 1 << (i % 10);
                const long long off = (long long)(i / 10) * 1023 + (d - 1);

                // -- A: K1 conv partials (4 pre + 4 stream) + ring push + wr --
                {
                    const float4* K1 = (const float4*)kern
                        + ((size_t)(i * 2 + 1) * 64 + kbc) * 32 + jqc;
                    float4 o0 = {0, 0, 0, 0};
                    mm_reg<4>(sx + kbc,     wk,          o0);
                    mm_gl<4> (sx + kbc + 4, K1 + 4 * 32, 32, o0);
                    *(float4*)&scp[ksc][4 * jqc] = o0;
                }
                if (tid < 64) {
                    size_t idx = ((size_t)row * RING_PER_ROW + (size_t)off
                                  + (t & (d - 1))) * 64 + c;
                    g_ring[idx] = sx[c];
                }
                wload<4>(wr, (const float4*)rw + (size_t)i * 64 * 16
                             + (size_t)kbr * 16 + jqr, 16);
                BAR_MAIN();

                // -- B: gate = K1 partials + lookahead K0 partials + bias --
                if (i < NLAYER - 1) {
                    const float4* KN = (const float4*)kern
                        + ((size_t)((i + 1) * 2 + 1) * 64 + kbc) * 32 + jqc;
                    wload<4>(wk, KN, 32);
                } else {
                    wload<8>(wk, (const float4*)ow0 + (size_t)khb * 64 + jqh, 64);
                }
                if (tid < 64) {
                    const int b = i & 1;
                    float p0 = scp[0][c], p1 = scp[1][c];
                    float p2 = scp[2][c], p3 = scp[3][c];
                    float p4 = scp[4][c], p5 = scp[5][c];
                    float p6 = scp[6][c], p7 = scp[7][c];
                    float q0 = scp[0][c+64], q1 = scp[1][c+64];
                    float q2 = scp[2][c+64], q3 = scp[3][c+64];
                    float q4 = scp[4][c+64], q5 = scp[5][c+64];
                    float q6 = scp[6][c+64], q7 = scp[7][c+64];
                    float k0t = (cp0[b][0][c]    + cp0[b][1][c])
                              + (cp0[b][2][c]    + cp0[b][3][c]);
                    float k0s = (cp0[b][0][c+64] + cp0[b][1][c+64])
                              + (cp0[b][2][c+64] + cp0[b][3][c+64]);
                    float ht = (((p0+p1)+(p2+p3)) + ((p4+p5)+(p6+p7)))
                             + k0t + cbs[i*128 + c];
                    float hs = (((q0+q1)+(q2+q3)) + ((q4+q5)+(q6+q7)))
                             + k0s + cbs[i*128 + 64 + c];
                    float e2 = __expf(2.f * ht);
                    float th = 1.f - __fdividef(2.f, e2 + 1.f);
                    float sig = __fdividef(1.f, 1.f + __expf(-hs));
                    sgb[b][c] = th * sig;
                }
                BAR_MAIN();

                // -- C: res partials (fully prefetched)
                {
                    float4 o0 = {0, 0, 0, 0};
                    mm_reg<4>(sgb[i & 1] + kbr, wr, o0);
                    *(float4*)&srp[ksr][4 * jqr] = o0;
                }
                BAR_MAIN();

                // -- D: x combine (tree-16)
                if (tid < 64) {
                    float a0 = srp[0][c] + srp[1][c];
                    float a1 = srp[2][c] + srp[3][c];
                    float a2 = srp[4][c] + srp[5][c];
                    float a3 = srp[6][c] + srp[7][c];
                    float a4 = srp[8][c] + srp[9][c];
                    float a5 = srp[10][c] + srp[11][c];
                    float a6 = srp[12][c] + srp[13][c];
                    float a7 = srp[14][c] + srp[15][c];
                    sx[c] += rb[i * 64 + c]
                           + (((a0+a1)+(a2+a3)) + ((a4+a5)+(a6+a7)));
                }
            } else {
                // ---- background: (1) K0 lookahead for layer j, (2) skip_{i-1}
                // j = i+1 within this step, or layer 0 of step t+1 at i=29.
                {
                    const int j  = (i + 1 < NLAYER) ? i + 1 : 0;
                    const int tt = (i + 1 < NLAYER) ? t : t + 1;
                    const int dj = 1 << (j % 10);
                    const long long offj = (long long)(j / 10) * 1023 + (dj - 1);
                    float4 o0 = {0, 0, 0, 0};
                    if (tt >= dj && tt < T) {
                        float a[16];
                        const float* src = g_ring
                            + ((size_t)row * RING_PER_ROW + (size_t)offj
                               + (tt & (dj - 1))) * 64 + kb0;
                        *(float4*)&a[0]  = *(const float4*)&src[0];
                        *(float4*)&a[4]  = *(const float4*)&src[4];
                        *(float4*)&a[8]  = *(const float4*)&src[8];
                        *(float4*)&a[12] = *(const float4*)&src[12];
                        const float4* K0 = (const float4*)kern
                            + ((size_t)(j * 2) * 64 + kb0) * 32 + jq0;
                        mm_ra<16>(a, K0, 32, o0);
                    }
                    *(float4*)&cp0[j & 1][ks0][4 * jq0] = o0;
                }
                if (i > 0) {
                    const float4* SW = (const float4*)sw
                        + ((size_t)(i - 1) * 64 + kbs) * 64 + jqs;
                    mm_gl<32>(sgb[(i - 1) & 1] + kbs, SW, 64, osk);
                }
            }
        }
        __syncthreads();   // P_30: layer 29 done; cp0[0] for t+1 written

        // ---- tail: skip_29 (background) while everyone prefetches head W0 ----
        wload<8>(wk, (const float4*)ow0 + (size_t)khb * 64 + jqh, 64);
        if (!is_main) {
            const float4* SW = (const float4*)sw
                + ((size_t)(NLAYER - 1) * 64 + kbs) * 64 + jqs;
            mm_gl<32>(sgb[(NLAYER - 1) & 1] + kbs, SW, 64, osk);
            *(float4*)&ssp[kss][4 * jqs] = osk;
        }
        __syncthreads();

        // ---- skip combine + Σbias + relu ----
        if (is_main) {
            float v0 = ssb[ch] + ssp[0][ch] + ssp[1][ch];
            ssk[ch] = fmaxf(v0, 0.f);
        }
        __syncthreads();

        // ---- head m0: h0 = relu(skip @ ow0 + ob0); all 384 threads ----
        {
            const float4* W = (const float4*)ow0 + (size_t)khb * 64 + jqh;
            float4 o0 = {0, 0, 0, 0};
            mm_reg<8>(ssk + khb, wk, o0);
            if (ksh < 4)
                mm_gl<40>(ssk + khb + 8, W + 8 * 64, 64, o0);
            else
                mm_gl<24>(ssk + khb + 8, W + 8 * 64, 64, o0);
            wload<8>(wk, (const float4*)ow1 + (size_t)khb * 64 + jqh, 64);
            *(float4*)&ssp[ksh][4 * jqh] = o0;
        }
        __syncthreads();
        if (is_main) {
            float v0 = obs0[ch] + (((ssp[0][ch] + ssp[1][ch])
                                  + (ssp[2][ch] + ssp[3][ch]))
                                  + (ssp[4][ch] + ssp[5][ch]));
            sh0[ch] = fmaxf(v0, 0.f);
        }
        __syncthreads();

        // ---- head m1: logits = h0 @ ow1 + ob1; all 384 threads ----
        {
            const float4* W = (const float4*)ow1 + (size_t)khb * 64 + jqh;
            float4 o0 = {0, 0, 0, 0};
            mm_reg<8>(sh0 + khb, wk, o0);
            if (ksh < 4)
                mm_gl<40>(sh0 + khb + 8, W + 8 * 64, 64, o0);
            else
                mm_gl<24>(sh0 + khb + 8, W + 8 * 64, 64, o0);
            // prefetch (t+1, layer 0) K1 conv weights
            if (is_main)
                wload<4>(wk, (const float4*)kern + (size_t)(64 + kbc) * 32 + jqc, 32);
            *(float4*)&ssp[ksh][4 * jqh] = o0;
        }
        __syncthreads();
        if (is_main) {
            float v0 = obs1[ch] + (((ssp[0][ch] + ssp[1][ch])
                                  + (ssp[2][ch] + ssp[3][ch]))
                                  + (ssp[4][ch] + ssp[5][ch]));
            slg[ch] = v0;
            if (mode & 2)
                out[logit_off + ((size_t)row * T + t) * VV + ch] = v0;
        }
        __syncthreads();

        // ---- argmax (first-max tie rule, matches jnp.argmax) ----
        if (tid < 32) {
            float bv = -FLT_MAX;
            int bi = 0;
#pragma unroll
            for (int jj = 0; jj < 8; jj++) {
                int j2 = tid + jj * 32;
                float v = slg[j2];
                if (v > bv) { bv = v; bi = j2; }
            }
#pragma unroll
            for (int o2 = 16; o2 > 0; o2 >>= 1) {
                float ov = __shfl_down_sync(0xffffffffu, bv, o2);
                int   oi = __shfl_down_sync(0xffffffffu, bi, o2);
                if (ov > bv || (ov == bv && oi < bi)) { bv = ov; bi = oi; }
            }
            if (tid == 0) {
                snidx = bi;
                if (mode & 1) out[samp_off + (size_t)row * T + t] = (float)bi;
                if (mode & 4) ((int*)out)[(size_t)row * T + t] = bi;
            }
        }
        __syncthreads();
    }
}

extern "C" void kernel_launch(void* const* d_in, const int* in_sizes, int n_in,
                              void* d_out, int out_size) {
    const int*   seed  = (const int*)d_in[0];
    const float* emb   = (const float*)d_in[1];
    const float* kern  = (const float*)d_in[2];
    const float* cbias = (const float*)d_in[3];
    const float* rw    = (const float*)d_in[4];
    const float* rb    = (const float*)d_in[5];
    const float* sw    = (const float*)d_in[6];
    const float* sb    = (const float*)d_in[7];
    const float* ow0   = (const float*)d_in[8];
    const float* ob0   = (const float*)d_in[9];
    const float* ow1   = (const float*)d_in[10];
    const float* ob1   = (const float*)d_in[11];
    (void)in_sizes; (void)n_in;

    int T, mode;
    long long samp_off = 0, logit_off = 0;
    if (out_size % (BB * (VV + 1)) == 0) {
        T = out_size / (BB * (VV + 1));
        mode = 1 | 2;                       // float samples then logits
        samp_off = 0;
        logit_off = (long long)BB * T;
    } else if (out_size % (BB * VV) == 0) {
        T = out_size / (BB * VV);
        mode = 2;                           // logits only
        logit_off = 0;
    } else {
        T = out_size / BB;
        mode = 4;                           // int32 samples only
    }

    wavenet_kernel<<<BB, 384>>>(seed, emb, kern, cbias, rw, rb, sw, sb,
                                ow0, ob0, ow1, ob1,
                                (float*)d_out, T, samp_off, logit_off, mode);
}